// round 5
// baseline (speedup 1.0000x reference)
#include <cuda_runtime.h>
#include <math.h>

#define BB 8
#define NN 2048
#define IND 128
#define OUTD 64
#define NEG_SLOPE 0.2f

// ---------------- scratch (static device globals; no allocations) ----------------
__device__ float g_hp[BB * NN * OUTD];           // projected features [row][dim] (4 MB)
__device__ float g_hpT[BB * OUTD * NN];          // transposed [b][dim][row] (4 MB)
__device__ float g_s[BB * NN];
__device__ float g_d[BB * NN];
__device__ float g_sortedD[BB * NN];
__device__ int   g_sortIdx[BB * NN];
__device__ float g_wp[BB * NN];                  // exp(d) at sorted position
__device__ float g_wq[BB * NN];                  // exp(0.2 d) at sorted position
__device__ float g_tabT[(size_t)BB * 130 * 2049];// [b][series][k] (8.5 MB)
__device__ float g_tab[(size_t)BB * 2049 * 130]; // [b][k][series] (8.5 MB)

// ---------------- kernel 1: hp = h @ W_fc + b_fc, fused s/d + transpose epilogue ----
__global__ void projectK(const float* __restrict__ h, const float* __restrict__ W,
                         const float* __restrict__ bfc,
                         const float* __restrict__ asrc, const float* __restrict__ adst) {
    extern __shared__ float sm[];
    float* sH = sm;                 // [64][128]  (32 KB)
    float* sW = sm + 64 * IND;      // [128][64]  (32 KB)
    const int t = threadIdx.x;
    const int rowBase = blockIdx.x * 64;

    const float4* hsrc = (const float4*)(h + (size_t)rowBase * IND);
    float4* sH4 = (float4*)sH;
#pragma unroll
    for (int i = t; i < 64 * IND / 4; i += 256) sH4[i] = hsrc[i];
    const float4* wsrc = (const float4*)W;
    float4* sW4 = (float4*)sW;
#pragma unroll
    for (int i = t; i < IND * OUTD / 4; i += 256) sW4[i] = wsrc[i];
    __syncthreads();

    const int q = t & 15;     // col quad
    const int g = t >> 4;     // row group
    const int c0 = q * 4;
    const int r0 = g * 4;

    const float4 b4 = *(const float4*)(bfc + c0);
    float acc[4][4];
#pragma unroll
    for (int r = 0; r < 4; r++) {
        acc[r][0] = b4.x; acc[r][1] = b4.y; acc[r][2] = b4.z; acc[r][3] = b4.w;
    }

    for (int k = 0; k < IND; k += 4) {
        float hv[4][4], wv[4][4];
#pragma unroll
        for (int r = 0; r < 4; r++) {
            const float4 a = *(const float4*)&sH[(r0 + r) * IND + k];
            hv[r][0] = a.x; hv[r][1] = a.y; hv[r][2] = a.z; hv[r][3] = a.w;
        }
#pragma unroll
        for (int kk = 0; kk < 4; kk++) {
            const float4 w = *(const float4*)&sW[(k + kk) * OUTD + c0];
            wv[kk][0] = w.x; wv[kk][1] = w.y; wv[kk][2] = w.z; wv[kk][3] = w.w;
        }
#pragma unroll
        for (int kk = 0; kk < 4; kk++)
#pragma unroll
            for (int r = 0; r < 4; r++)
#pragma unroll
                for (int c = 0; c < 4; c++)
                    acc[r][c] = fmaf(hv[r][kk], wv[kk][c], acc[r][c]);
    }

    float* outp = g_hp + (size_t)rowBase * OUTD;
#pragma unroll
    for (int r = 0; r < 4; r++) {
        float4 o; o.x = acc[r][0]; o.y = acc[r][1]; o.z = acc[r][2]; o.w = acc[r][3];
        *(float4*)&outp[(size_t)(r0 + r) * OUTD + c0] = o;
    }

    // ---- fused s/d epilogue ----
    const float4 as4 = *(const float4*)(asrc + c0);
    const float4 ad4 = *(const float4*)(adst + c0);
    float sp[4], dp[4];
#pragma unroll
    for (int r = 0; r < 4; r++) {
        sp[r] = fmaf(acc[r][0], as4.x, fmaf(acc[r][1], as4.y,
                 fmaf(acc[r][2], as4.z, acc[r][3] * as4.w)));
        dp[r] = fmaf(acc[r][0], ad4.x, fmaf(acc[r][1], ad4.y,
                 fmaf(acc[r][2], ad4.z, acc[r][3] * ad4.w)));
    }
#pragma unroll
    for (int o = 1; o < 16; o <<= 1) {
#pragma unroll
        for (int r = 0; r < 4; r++) {
            sp[r] += __shfl_xor_sync(0xffffffffu, sp[r], o);
            dp[r] += __shfl_xor_sync(0xffffffffu, dp[r], o);
        }
    }
    if (q == 0) {
#pragma unroll
        for (int r = 0; r < 4; r++) {
            g_s[rowBase + r0 + r] = sp[r];
            g_d[rowBase + r0 + r] = dp[r];
        }
    }

    // ---- transpose epilogue: emit g_hpT[b][dim][row] ----
    __syncthreads();                    // done reading sH
    float* tile = sm;                   // [64 dims][65 pad]  (16.6 KB)
#pragma unroll
    for (int r = 0; r < 4; r++)
#pragma unroll
        for (int c = 0; c < 4; c++)
            tile[(c0 + c) * 65 + (r0 + r)] = acc[r][c];
    __syncthreads();

    const int b = rowBase >> 11;
    const int rib = rowBase & (NN - 1);
    for (int f = t; f < 64 * 64; f += 256) {
        const int dim = f >> 6, i = f & 63;
        g_hpT[((size_t)(b * OUTD + dim)) * NN + rib + i] = tile[dim * 65 + i];
    }
}

// ---------------- kernel 2: per-batch bitonic sort, packed 64-bit (key|idx) ----------------
__global__ void sortK() {
    const int b = blockIdx.x;
    __shared__ unsigned long long su[NN];
    const int t = threadIdx.x;  // 1024

    for (int i = t; i < NN; i += 1024) {
        const unsigned bits = __float_as_uint(g_d[b * NN + i]);
        const unsigned key = bits ^ ((bits & 0x80000000u) ? 0xFFFFFFFFu : 0x80000000u);
        su[i] = ((unsigned long long)key << 32) | (unsigned)i;
    }
    __syncthreads();

    for (int k = 2; k <= NN; k <<= 1) {
        for (int j = k >> 1; j > 0; j >>= 1) {
            const int i = ((t & ~(j - 1)) << 1) | (t & (j - 1));
            const int partner = i | j;
            const bool up = ((i & k) == 0);
            const unsigned long long A = su[i], B = su[partner];
            const unsigned long long lo_ = (A < B) ? A : B;
            const unsigned long long hi_ = (A < B) ? B : A;
            su[i] = up ? lo_ : hi_;
            su[partner] = up ? hi_ : lo_;
            if (j >= 64) __syncthreads(); else __syncwarp();
        }
        __syncthreads();
    }

    for (int i = t; i < NN; i += 1024) {
        const unsigned long long u = su[i];
        const unsigned key = (unsigned)(u >> 32);
        const unsigned bits = key ^ ((key & 0x80000000u) ? 0x80000000u : 0xFFFFFFFFu);
        const float dv = __uint_as_float(bits);
        g_sortedD[b * NN + i] = dv;
        g_sortIdx[b * NN + i] = (int)(u & 0xFFFFFFFFu);
        g_wp[b * NN + i] = __expf(dv);
        g_wq[b * NN + i] = __expf(NEG_SLOPE * dv);
    }
}

// ---------------- kernel 3: fused dual scan, L1-local gather, coalesced tabT writes ----
// block = (b, dim) : 520 blocks x 256 threads, 8 consecutive positions per thread.
__global__ void scanK() {
    const int blk = blockIdx.x;
    const int b = blk / 65;
    const int dim = blk - b * 65;
    const int t = threadIdx.x;
    const int lane = t & 31, warp = t >> 5;
    const int base = b * NN;
    const float* __restrict__ hprow = g_hpT + ((size_t)(b * OUTD + dim)) * NN;

    float vp[8], vn[8];
#pragma unroll
    for (int e = 0; e < 8; e++) {
        const int r = t * 8 + e;
        const float wpv = g_wp[base + r];
        const float wqv = g_wq[base + r];
        float val = 1.0f;
        if (dim < 64) val = hprow[g_sortIdx[base + r]];   // scattered in one 8KB row
        vp[e] = wpv * val;
        vn[e] = wqv * val;
    }

#pragma unroll
    for (int e = 1; e < 8; e++) vn[e] += vn[e - 1];       // fwd inclusive (neg)
#pragma unroll
    for (int e = 6; e >= 0; e--) vp[e] += vp[e + 1];      // bwd inclusive (pos)
    const float totn = vn[7], totp = vp[0];

    __shared__ float wtn[8], wtp[8];
    float xn = totn, xp = totp;
#pragma unroll
    for (int o = 1; o < 32; o <<= 1) {
        const float yn = __shfl_up_sync(0xffffffffu, xn, o);
        if (lane >= o) xn += yn;
        const float yp = __shfl_down_sync(0xffffffffu, xp, o);
        if (lane < 32 - o) xp += yp;
    }
    if (lane == 31) wtn[warp] = xn;
    if (lane == 0)  wtp[warp] = xp;
    __syncthreads();

    float offn = 0.f, offp = 0.f;
#pragma unroll
    for (int w2 = 0; w2 < 8; w2++) {
        if (w2 < warp) offn += wtn[w2];
        if (w2 > warp) offp += wtp[w2];
    }
    const float basen = offn + xn - totn;
    const float basep = offp + xp - totp;

    float* __restrict__ tp = g_tabT + ((size_t)(b * 130 + dim)) * 2049;
    float* __restrict__ tn = g_tabT + ((size_t)(b * 130 + 65 + dim)) * 2049;
#pragma unroll
    for (int e = 0; e < 8; e++) {
        const int k = t * 8 + e;
        tp[k] = basep + vp[e];        // sufPos[k]
        tn[k + 1] = basen + vn[e];    // prefNeg[k+1]
    }
    if (t == 0) { tp[2048] = 0.f; tn[0] = 0.f; }
}

// ---------------- kernel 4: tiled transpose tabT -> tab (both sides coalesced) --------
__global__ void transK() {
    __shared__ float tile[64 * 131];
    const int b = blockIdx.y;
    const int k0 = blockIdx.x * 64;
    const int t = threadIdx.x;   // 256

    for (int f = t; f < 130 * 64; f += 256) {
        const int s = f >> 6, kk = f & 63;
        const int k = k0 + kk;
        tile[kk * 131 + s] = (k < 2049)
            ? g_tabT[((size_t)(b * 130 + s)) * 2049 + k] : 0.f;
    }
    __syncthreads();
    for (int f = t; f < 64 * 130; f += 256) {
        const int kk = f / 130, s = f - kk * 130;
        const int k = k0 + kk;
        if (k < 2049)
            g_tab[((size_t)(b * 2049 + k)) * 130 + s] = tile[kk * 131 + s];
    }
}

// ---------------- kernel 5: per-row output (128 rows/block) ----------------
__global__ void outK(const float* __restrict__ battn, float* __restrict__ out) {
    __shared__ float sd[NN];
    __shared__ float ssi[128];
    __shared__ int slo[128];
    const int b = blockIdx.x >> 4;
    const int rb = (blockIdx.x & 15) * 128;
    const int t = threadIdx.x;   // 256

    const float4* src = (const float4*)(g_sortedD + b * NN);
    float4* dst = (float4*)sd;
    for (int i = t; i < NN / 4; i += 256) dst[i] = src[i];
    __syncthreads();

    if (t < 128) {
        const float si = g_s[b * NN + rb + t] + *battn;
        const float tt = -si;
        int lo = 0, hi = NN;
        while (lo < hi) {
            const int mid = (lo + hi) >> 1;
            if (sd[mid] < tt) lo = mid + 1; else hi = mid;
        }
        ssi[t] = si; slo[t] = lo;
    }
    __syncthreads();

    const int warp = t >> 5, lane = t & 31;
#pragma unroll 2
    for (int rr = 0; rr < 16; rr++) {
        const int lr = warp * 16 + rr;
        const int row = b * NN + rb + lr;
        const float s2 = ssi[lr];
        const float P = __expf(s2);
        const float Q = __expf(NEG_SLOPE * s2);
        const float* tb = g_tab + ((size_t)b * 2049 + slo[lr]) * 130;
        const float den = fmaf(P, tb[64], Q * tb[129]);
        const float inv = 1.0f / den;
        float* orow = out + (size_t)row * OUTD;
#pragma unroll
        for (int d0 = 0; d0 < 2; d0++) {
            const int d = lane + d0 * 32;
            const float num = fmaf(P, tb[d], Q * tb[65 + d]);
            const float o = num * inv;
            orow[d] = (o > 0.f) ? o : (__expf(o) - 1.0f);   // ELU (alpha=1)
        }
    }
}

// ---------------- launch ----------------
extern "C" void kernel_launch(void* const* d_in, const int* in_sizes, int n_in,
                              void* d_out, int out_size) {
    const float* h     = (const float*)d_in[0];
    const float* W     = (const float*)d_in[1];
    const float* bfc   = (const float*)d_in[2];
    const float* asrc  = (const float*)d_in[3];
    const float* adst  = (const float*)d_in[4];
    const float* battn = (const float*)d_in[5];
    float* out = (float*)d_out;

    cudaFuncSetAttribute(projectK, cudaFuncAttributeMaxDynamicSharedMemorySize, 64 * 1024);

    projectK<<<(BB * NN) / 64, 256, 64 * 1024>>>(h, W, bfc, asrc, adst);
    sortK<<<BB, 1024>>>();
    scanK<<<BB * 65, 256>>>();
    dim3 tg(33, BB);
    transK<<<tg, 256>>>();
    outK<<<(BB * NN) / 128, 256>>>(battn, out);
}

// round 6
// speedup vs baseline: 1.6214x; 1.6214x over previous
#include <cuda_runtime.h>
#include <math.h>

#define BB 8
#define NN 2048
#define IND 128
#define OUTD 64
#define NEG_SLOPE 0.2f

// ---------------- scratch (static device globals; no allocations) ----------------
__device__ float g_hp[BB * NN * OUTD];           // projected features [row][dim] (4 MB)
__device__ float g_hpT[BB * OUTD * NN];          // transposed [b][dim][row] (4 MB)
__device__ float g_s[BB * NN];
__device__ float g_d[BB * NN];
__device__ float g_sortedD[BB * NN];
__device__ int   g_sortIdx[BB * NN];
__device__ float g_wp[BB * NN];                  // exp(d) at sorted position
__device__ float g_wq[BB * NN];                  // exp(0.2 d) at sorted position
__device__ float g_tab[(size_t)BB * 2049 * 130]; // [b][k][0..64]=sufPos, [65..129]=prefNeg

// ---------------- kernel 1: hp = h @ W_fc + b_fc, fused s/d + hpT epilogues ----------
__global__ void projectK(const float* __restrict__ h, const float* __restrict__ W,
                         const float* __restrict__ bfc,
                         const float* __restrict__ asrc, const float* __restrict__ adst) {
    extern __shared__ float sm[];
    float* sH = sm;                 // [64][128]  (32 KB)
    float* sW = sm + 64 * IND;      // [128][64]  (32 KB)
    const int t = threadIdx.x;
    const int rowBase = blockIdx.x * 64;

    const float4* hsrc = (const float4*)(h + (size_t)rowBase * IND);
    float4* sH4 = (float4*)sH;
#pragma unroll
    for (int i = t; i < 64 * IND / 4; i += 256) sH4[i] = hsrc[i];
    const float4* wsrc = (const float4*)W;
    float4* sW4 = (float4*)sW;
#pragma unroll
    for (int i = t; i < IND * OUTD / 4; i += 256) sW4[i] = wsrc[i];
    __syncthreads();

    const int q = t & 15;     // col quad: cols 4q..4q+3
    const int g = t >> 4;     // row group: rows 4g..4g+3
    const int c0 = q * 4;
    const int r0 = g * 4;

    const float4 b4 = *(const float4*)(bfc + c0);
    float acc[4][4];
#pragma unroll
    for (int r = 0; r < 4; r++) {
        acc[r][0] = b4.x; acc[r][1] = b4.y; acc[r][2] = b4.z; acc[r][3] = b4.w;
    }

    for (int k = 0; k < IND; k += 4) {
        float hv[4][4], wv[4][4];
#pragma unroll
        for (int r = 0; r < 4; r++) {
            const float4 a = *(const float4*)&sH[(r0 + r) * IND + k];
            hv[r][0] = a.x; hv[r][1] = a.y; hv[r][2] = a.z; hv[r][3] = a.w;
        }
#pragma unroll
        for (int kk = 0; kk < 4; kk++) {
            const float4 w = *(const float4*)&sW[(k + kk) * OUTD + c0];
            wv[kk][0] = w.x; wv[kk][1] = w.y; wv[kk][2] = w.z; wv[kk][3] = w.w;
        }
#pragma unroll
        for (int kk = 0; kk < 4; kk++)
#pragma unroll
            for (int r = 0; r < 4; r++)
#pragma unroll
                for (int c = 0; c < 4; c++)
                    acc[r][c] = fmaf(hv[r][kk], wv[kk][c], acc[r][c]);
    }

    float* outp = g_hp + (size_t)rowBase * OUTD;
#pragma unroll
    for (int r = 0; r < 4; r++) {
        float4 o; o.x = acc[r][0]; o.y = acc[r][1]; o.z = acc[r][2]; o.w = acc[r][3];
        *(float4*)&outp[(size_t)(r0 + r) * OUTD + c0] = o;
    }

    // ---- fused s/d epilogue: 16-lane shuffle reduce across col-quads ----
    const float4 as4 = *(const float4*)(asrc + c0);
    const float4 ad4 = *(const float4*)(adst + c0);
    float sp[4], dp[4];
#pragma unroll
    for (int r = 0; r < 4; r++) {
        sp[r] = fmaf(acc[r][0], as4.x, fmaf(acc[r][1], as4.y,
                 fmaf(acc[r][2], as4.z, acc[r][3] * as4.w)));
        dp[r] = fmaf(acc[r][0], ad4.x, fmaf(acc[r][1], ad4.y,
                 fmaf(acc[r][2], ad4.z, acc[r][3] * ad4.w)));
    }
#pragma unroll
    for (int o = 1; o < 16; o <<= 1) {
#pragma unroll
        for (int r = 0; r < 4; r++) {
            sp[r] += __shfl_xor_sync(0xffffffffu, sp[r], o);
            dp[r] += __shfl_xor_sync(0xffffffffu, dp[r], o);
        }
    }
    if (q == 0) {
#pragma unroll
        for (int r = 0; r < 4; r++) {
            g_s[rowBase + r0 + r] = sp[r];
            g_d[rowBase + r0 + r] = dp[r];
        }
    }

    // ---- transpose epilogue: emit g_hpT[b][dim][row] ----
    __syncthreads();                    // done reading sH
    float* tile = sm;                   // [64 dims][65 pad]
#pragma unroll
    for (int r = 0; r < 4; r++)
#pragma unroll
        for (int c = 0; c < 4; c++)
            tile[(c0 + c) * 65 + (r0 + r)] = acc[r][c];
    __syncthreads();

    const int b = rowBase >> 11;
    const int rib = rowBase & (NN - 1);
    for (int f = t; f < 64 * 64; f += 256) {
        const int dim = f >> 6, i = f & 63;
        g_hpT[((size_t)(b * OUTD + dim)) * NN + rib + i] = tile[dim * 65 + i];
    }
}

// ---------------- kernel 2: per-batch bitonic sort, packed 64-bit (key|idx) ----------------
__global__ void sortK() {
    const int b = blockIdx.x;
    __shared__ unsigned long long su[NN];
    const int t = threadIdx.x;  // 1024

    for (int i = t; i < NN; i += 1024) {
        const unsigned bits = __float_as_uint(g_d[b * NN + i]);
        const unsigned key = bits ^ ((bits & 0x80000000u) ? 0xFFFFFFFFu : 0x80000000u);
        su[i] = ((unsigned long long)key << 32) | (unsigned)i;
    }
    __syncthreads();

    for (int k = 2; k <= NN; k <<= 1) {
        for (int j = k >> 1; j > 0; j >>= 1) {
            const int i = ((t & ~(j - 1)) << 1) | (t & (j - 1));
            const int partner = i | j;
            const bool up = ((i & k) == 0);
            const unsigned long long A = su[i], B = su[partner];
            const unsigned long long lo_ = (A < B) ? A : B;
            const unsigned long long hi_ = (A < B) ? B : A;
            su[i] = up ? lo_ : hi_;
            su[partner] = up ? hi_ : lo_;
            if (j >= 64) __syncthreads(); else __syncwarp();
        }
        __syncthreads();
    }

    for (int i = t; i < NN; i += 1024) {
        const unsigned long long u = su[i];
        const unsigned key = (unsigned)(u >> 32);
        const unsigned bits = key ^ ((key & 0x80000000u) ? 0x80000000u : 0xFFFFFFFFu);
        const float dv = __uint_as_float(bits);
        g_sortedD[b * NN + i] = dv;
        g_sortIdx[b * NN + i] = (int)(u & 0xFFFFFFFFu);
        g_wp[b * NN + i] = __expf(dv);
        g_wq[b * NN + i] = __expf(NEG_SLOPE * dv);
    }
}

// ---------------- kernel 3: fused dual scan (R2 structure), hpT-row gather ----------
// block = (b, dim). 256 threads x 8 consecutive sorted positions each.
__global__ void scanK() {
    const int blk = blockIdx.x;          // 0..519
    const int b = blk / 65;
    const int dim = blk - b * 65;
    const int t = threadIdx.x;
    const int lane = t & 31, warp = t >> 5;
    const int base = b * NN;
    const float* __restrict__ hprow = g_hpT + ((size_t)(b * OUTD + dim)) * NN;

    float vp[8], vn[8];
#pragma unroll
    for (int e = 0; e < 8; e++) {
        const int r = t * 8 + e;
        const float wpv = g_wp[base + r];
        const float wqv = g_wq[base + r];
        float val = 1.0f;
        if (dim < 64) val = hprow[g_sortIdx[base + r]];  // scattered within one 8KB L1-resident row
        vp[e] = wpv * val;
        vn[e] = wqv * val;
    }

    // neg: forward inclusive within chunk; pos: backward inclusive (suffix)
#pragma unroll
    for (int e = 1; e < 8; e++) vn[e] += vn[e - 1];
#pragma unroll
    for (int e = 6; e >= 0; e--) vp[e] += vp[e + 1];
    const float totn = vn[7], totp = vp[0];

    __shared__ float wtn[8], wtp[8];
    float xn = totn, xp = totp;
#pragma unroll
    for (int o = 1; o < 32; o <<= 1) {
        const float yn = __shfl_up_sync(0xffffffffu, xn, o);
        if (lane >= o) xn += yn;
        const float yp = __shfl_down_sync(0xffffffffu, xp, o);
        if (lane < 32 - o) xp += yp;
    }
    if (lane == 31) wtn[warp] = xn;
    if (lane == 0)  wtp[warp] = xp;
    __syncthreads();

    float offn = 0.f, offp = 0.f;
#pragma unroll
    for (int w2 = 0; w2 < 8; w2++) {
        if (w2 < warp) offn += wtn[w2];
        if (w2 > warp) offp += wtp[w2];
    }
    const float basen = offn + xn - totn;   // sum strictly before this chunk
    const float basep = offp + xp - totp;   // sum strictly after this chunk

    float* tabb = g_tab + (size_t)b * 2049 * 130;
#pragma unroll
    for (int e = 0; e < 8; e++) {
        const int kp = t * 8 + e;
        tabb[(size_t)kp * 130 + dim] = basep + vp[e];              // sufPos[k]
        tabb[(size_t)(kp + 1) * 130 + 65 + dim] = basen + vn[e];   // prefNeg[k+1]
    }
    if (t == 0) {
        tabb[(size_t)2048 * 130 + dim] = 0.f;        // sufPos[2048]
        tabb[65 + dim] = 0.f;                        // prefNeg[0]
    }
}

// ---------------- kernel 4: per-row output (128 rows/block) ----------------
__global__ void outK(const float* __restrict__ battn, float* __restrict__ out) {
    __shared__ float sd[NN];
    __shared__ float ssi[128];
    __shared__ int slo[128];
    const int b = blockIdx.x >> 4;                  // 16 blocks per batch
    const int rb = (blockIdx.x & 15) * 128;         // row base within batch
    const int t = threadIdx.x;                      // 256

    const float4* src = (const float4*)(g_sortedD + b * NN);
    float4* dst = (float4*)sd;
    for (int i = t; i < NN / 4; i += 256) dst[i] = src[i];
    __syncthreads();

    if (t < 128) {
        const float si = g_s[b * NN + rb + t] + *battn;
        const float tt = -si;                       // d_j >= tt -> positive branch
        int lo = 0, hi = NN;
        while (lo < hi) {
            const int mid = (lo + hi) >> 1;
            if (sd[mid] < tt) lo = mid + 1; else hi = mid;
        }
        ssi[t] = si; slo[t] = lo;
    }
    __syncthreads();

    const int warp = t >> 5, lane = t & 31;
#pragma unroll 2
    for (int rr = 0; rr < 16; rr++) {
        const int lr = warp * 16 + rr;
        const int row = b * NN + rb + lr;
        const float s2 = ssi[lr];
        const float P = __expf(s2);
        const float Q = __expf(NEG_SLOPE * s2);
        const float* tb = g_tab + ((size_t)b * 2049 + slo[lr]) * 130;
        const float den = fmaf(P, tb[64], Q * tb[129]);
        const float inv = 1.0f / den;
        float* orow = out + (size_t)row * OUTD;
#pragma unroll
        for (int d0 = 0; d0 < 2; d0++) {
            const int d = lane + d0 * 32;
            const float num = fmaf(P, tb[d], Q * tb[65 + d]);
            const float o = num * inv;
            orow[d] = (o > 0.f) ? o : (__expf(o) - 1.0f);   // ELU (alpha=1)
        }
    }
}

// ---------------- launch ----------------
extern "C" void kernel_launch(void* const* d_in, const int* in_sizes, int n_in,
                              void* d_out, int out_size) {
    const float* h     = (const float*)d_in[0];
    const float* W     = (const float*)d_in[1];
    const float* bfc   = (const float*)d_in[2];
    const float* asrc  = (const float*)d_in[3];
    const float* adst  = (const float*)d_in[4];
    const float* battn = (const float*)d_in[5];
    float* out = (float*)d_out;

    cudaFuncSetAttribute(projectK, cudaFuncAttributeMaxDynamicSharedMemorySize, 64 * 1024);

    projectK<<<(BB * NN) / 64, 256, 64 * 1024>>>(h, W, bfc, asrc, adst);
    sortK<<<BB, 1024>>>();
    scanK<<<BB * 65, 256>>>();
    outK<<<(BB * NN) / 128, 256>>>(battn, out);
}

// round 8
// speedup vs baseline: 1.8009x; 1.1107x over previous
#include <cuda_runtime.h>
#include <math.h>

#define BB 8
#define NN 2048
#define IND 128
#define OUTD 64
#define NEG_SLOPE 0.2f

// ---------------- scratch (static device globals; no allocations) ----------------
__device__ float g_hp[BB * NN * OUTD];           // projected features [row][dim] (4 MB)
__device__ float g_hpT[BB * OUTD * NN];          // transposed [b][dim][row] (4 MB)
__device__ float g_s[BB * NN];
__device__ float g_d[BB * NN];
__device__ float g_sortedD[BB * NN];
__device__ int   g_sortIdx[BB * NN];
__device__ float g_wp[BB * NN];                  // exp(d) at sorted position
__device__ float g_wq[BB * NN];                  // exp(0.2 d) at sorted position
__device__ float g_tab[(size_t)BB * 2049 * 130]; // [b][k][0..64]=sufPos, [65..129]=prefNeg

// ---------------- kernel 1: hp = h @ W_fc + b_fc, fused s/d + hpT epilogues ----------
__global__ void projectK(const float* __restrict__ h, const float* __restrict__ W,
                         const float* __restrict__ bfc,
                         const float* __restrict__ asrc, const float* __restrict__ adst) {
    extern __shared__ float sm[];
    float* sH = sm;                 // [64][128]  (32 KB)
    float* sW = sm + 64 * IND;      // [128][64]  (32 KB)
    const int t = threadIdx.x;
    const int rowBase = blockIdx.x * 64;

    const float4* hsrc = (const float4*)(h + (size_t)rowBase * IND);
    float4* sH4 = (float4*)sH;
#pragma unroll
    for (int i = t; i < 64 * IND / 4; i += 256) sH4[i] = hsrc[i];
    const float4* wsrc = (const float4*)W;
    float4* sW4 = (float4*)sW;
#pragma unroll
    for (int i = t; i < IND * OUTD / 4; i += 256) sW4[i] = wsrc[i];
    __syncthreads();

    const int q = t & 15;     // col quad: cols 4q..4q+3
    const int g = t >> 4;     // row group: rows 4g..4g+3
    const int c0 = q * 4;
    const int r0 = g * 4;

    const float4 b4 = *(const float4*)(bfc + c0);
    float acc[4][4];
#pragma unroll
    for (int r = 0; r < 4; r++) {
        acc[r][0] = b4.x; acc[r][1] = b4.y; acc[r][2] = b4.z; acc[r][3] = b4.w;
    }

    for (int k = 0; k < IND; k += 4) {
        float hv[4][4], wv[4][4];
#pragma unroll
        for (int r = 0; r < 4; r++) {
            const float4 a = *(const float4*)&sH[(r0 + r) * IND + k];
            hv[r][0] = a.x; hv[r][1] = a.y; hv[r][2] = a.z; hv[r][3] = a.w;
        }
#pragma unroll
        for (int kk = 0; kk < 4; kk++) {
            const float4 w = *(const float4*)&sW[(k + kk) * OUTD + c0];
            wv[kk][0] = w.x; wv[kk][1] = w.y; wv[kk][2] = w.z; wv[kk][3] = w.w;
        }
#pragma unroll
        for (int kk = 0; kk < 4; kk++)
#pragma unroll
            for (int r = 0; r < 4; r++)
#pragma unroll
                for (int c = 0; c < 4; c++)
                    acc[r][c] = fmaf(hv[r][kk], wv[kk][c], acc[r][c]);
    }

    float* outp = g_hp + (size_t)rowBase * OUTD;
#pragma unroll
    for (int r = 0; r < 4; r++) {
        float4 o; o.x = acc[r][0]; o.y = acc[r][1]; o.z = acc[r][2]; o.w = acc[r][3];
        *(float4*)&outp[(size_t)(r0 + r) * OUTD + c0] = o;
    }

    // ---- fused s/d epilogue: 16-lane shuffle reduce across col-quads ----
    const float4 as4 = *(const float4*)(asrc + c0);
    const float4 ad4 = *(const float4*)(adst + c0);
    float sp[4], dp[4];
#pragma unroll
    for (int r = 0; r < 4; r++) {
        sp[r] = fmaf(acc[r][0], as4.x, fmaf(acc[r][1], as4.y,
                 fmaf(acc[r][2], as4.z, acc[r][3] * as4.w)));
        dp[r] = fmaf(acc[r][0], ad4.x, fmaf(acc[r][1], ad4.y,
                 fmaf(acc[r][2], ad4.z, acc[r][3] * ad4.w)));
    }
#pragma unroll
    for (int o = 1; o < 16; o <<= 1) {
#pragma unroll
        for (int r = 0; r < 4; r++) {
            sp[r] += __shfl_xor_sync(0xffffffffu, sp[r], o);
            dp[r] += __shfl_xor_sync(0xffffffffu, dp[r], o);
        }
    }
    if (q == 0) {
#pragma unroll
        for (int r = 0; r < 4; r++) {
            g_s[rowBase + r0 + r] = sp[r];
            g_d[rowBase + r0 + r] = dp[r];
        }
    }

    // ---- transpose epilogue: emit g_hpT[b][dim][row] ----
    __syncthreads();                    // done reading sH
    float* tile = sm;                   // [64 dims][65 pad]
#pragma unroll
    for (int r = 0; r < 4; r++)
#pragma unroll
        for (int c = 0; c < 4; c++)
            tile[(c0 + c) * 65 + (r0 + r)] = acc[r][c];
    __syncthreads();

    const int b = rowBase >> 11;
    const int rib = rowBase & (NN - 1);
    for (int f = t; f < 64 * 64; f += 256) {
        const int dim = f >> 6, i = f & 63;
        g_hpT[((size_t)(b * OUTD + dim)) * NN + rib + i] = tile[dim * 65 + i];
    }
}

// ---------------- kernel 2: per-batch bitonic sort, packed 64-bit (key|idx) ----------------
__global__ void sortK() {
    const int b = blockIdx.x;
    __shared__ unsigned long long su[NN];
    const int t = threadIdx.x;  // 1024

    for (int i = t; i < NN; i += 1024) {
        const unsigned bits = __float_as_uint(g_d[b * NN + i]);
        const unsigned key = bits ^ ((bits & 0x80000000u) ? 0xFFFFFFFFu : 0x80000000u);
        su[i] = ((unsigned long long)key << 32) | (unsigned)i;
    }
    __syncthreads();

    for (int k = 2; k <= NN; k <<= 1) {
        for (int j = k >> 1; j > 0; j >>= 1) {
            const int i = ((t & ~(j - 1)) << 1) | (t & (j - 1));
            const int partner = i | j;
            const bool up = ((i & k) == 0);
            const unsigned long long A = su[i], B = su[partner];
            const unsigned long long lo_ = (A < B) ? A : B;
            const unsigned long long hi_ = (A < B) ? B : A;
            su[i] = up ? lo_ : hi_;
            su[partner] = up ? hi_ : lo_;
            if (j >= 64) __syncthreads(); else __syncwarp();
        }
        __syncthreads();
    }

    for (int i = t; i < NN; i += 1024) {
        const unsigned long long u = su[i];
        const unsigned key = (unsigned)(u >> 32);
        const unsigned bits = key ^ ((key & 0x80000000u) ? 0x80000000u : 0xFFFFFFFFu);
        const float dv = __uint_as_float(bits);
        g_sortedD[b * NN + i] = dv;
        g_sortIdx[b * NN + i] = (int)(u & 0xFFFFFFFFu);
        g_wp[b * NN + i] = __expf(dv);
        g_wq[b * NN + i] = __expf(NEG_SLOPE * dv);
    }
}

// ---------------- kernel 3: fused dual scan, hpT-row gather (L1-resident) ----------
// block = (b, dim). 256 threads x 8 consecutive sorted positions each.
__global__ void scanK() {
    const int blk = blockIdx.x;          // 0..519
    const int b = blk / 65;
    const int dim = blk - b * 65;
    const int t = threadIdx.x;
    const int lane = t & 31, warp = t >> 5;
    const int base = b * NN;
    const float* __restrict__ hprow = g_hpT + ((size_t)(b * OUTD + dim)) * NN;

    float vp[8], vn[8];
#pragma unroll
    for (int e = 0; e < 8; e++) {
        const int r = t * 8 + e;
        const float wpv = g_wp[base + r];
        const float wqv = g_wq[base + r];
        float val = 1.0f;
        if (dim < 64) val = hprow[g_sortIdx[base + r]];  // scattered within one 8KB L1-resident row
        vp[e] = wpv * val;
        vn[e] = wqv * val;
    }

    // neg: forward inclusive within chunk; pos: backward inclusive (suffix)
#pragma unroll
    for (int e = 1; e < 8; e++) vn[e] += vn[e - 1];
#pragma unroll
    for (int e = 6; e >= 0; e--) vp[e] += vp[e + 1];
    const float totn = vn[7], totp = vp[0];

    __shared__ float wtn[8], wtp[8];
    float xn = totn, xp = totp;
#pragma unroll
    for (int o = 1; o < 32; o <<= 1) {
        const float yn = __shfl_up_sync(0xffffffffu, xn, o);
        if (lane >= o) xn += yn;
        const float yp = __shfl_down_sync(0xffffffffu, xp, o);
        if (lane < 32 - o) xp += yp;
    }
    if (lane == 31) wtn[warp] = xn;
    if (lane == 0)  wtp[warp] = xp;
    __syncthreads();

    float offn = 0.f, offp = 0.f;
#pragma unroll
    for (int w2 = 0; w2 < 8; w2++) {
        if (w2 < warp) offn += wtn[w2];
        if (w2 > warp) offp += wtp[w2];
    }
    const float basen = offn + xn - totn;   // sum strictly before this chunk
    const float basep = offp + xp - totp;   // sum strictly after this chunk

    float* tabb = g_tab + (size_t)b * 2049 * 130;
#pragma unroll
    for (int e = 0; e < 8; e++) {
        const int kp = t * 8 + e;
        tabb[(size_t)kp * 130 + dim] = basep + vp[e];              // sufPos[k]
        tabb[(size_t)(kp + 1) * 130 + 65 + dim] = basen + vn[e];   // prefNeg[k+1]
    }
    if (t == 0) {
        tabb[(size_t)2048 * 130 + dim] = 0.f;        // sufPos[2048]
        tabb[65 + dim] = 0.f;                        // prefNeg[0]
    }
}

// ---------------- kernel 4: per-row output — one warp per row, no staging ----------
__global__ void outK(const float* __restrict__ battn, float* __restrict__ out) {
    const int warp = threadIdx.x >> 5, lane = threadIdx.x & 31;
    const int row = blockIdx.x * 8 + warp;
    const int b = row >> 11;                       // NN = 2048

    // all lanes run the same search (uniform addresses -> broadcast transactions)
    const float si = g_s[row] + *battn;
    const float tt = -si;                          // d_j >= tt -> positive branch
    const float* __restrict__ sd = g_sortedD + b * NN;
    int lo = 0, hi = NN;
    while (lo < hi) {
        const int mid = (lo + hi) >> 1;
        if (sd[mid] < tt) lo = mid + 1; else hi = mid;
    }

    const float P = __expf(si);
    const float Q = __expf(NEG_SLOPE * si);
    const float* __restrict__ tb = g_tab + ((size_t)b * 2049 + lo) * 130;
    const float den = fmaf(P, tb[64], Q * tb[129]);
    const float inv = 1.0f / den;

    float* orow = out + (size_t)row * OUTD;
#pragma unroll
    for (int d0 = 0; d0 < 2; d0++) {
        const int d = lane + d0 * 32;
        const float num = fmaf(P, tb[d], Q * tb[65 + d]);
        const float o = num * inv;
        orow[d] = (o > 0.f) ? o : (__expf(o) - 1.0f);   // ELU (alpha=1)
    }
}

// ---------------- launch ----------------
extern "C" void kernel_launch(void* const* d_in, const int* in_sizes, int n_in,
                              void* d_out, int out_size) {
    const float* h     = (const float*)d_in[0];
    const float* W     = (const float*)d_in[1];
    const float* bfc   = (const float*)d_in[2];
    const float* asrc  = (const float*)d_in[3];
    const float* adst  = (const float*)d_in[4];
    const float* battn = (const float*)d_in[5];
    float* out = (float*)d_out;

    cudaFuncSetAttribute(projectK, cudaFuncAttributeMaxDynamicSharedMemorySize, 64 * 1024);

    projectK<<<(BB * NN) / 64, 256, 64 * 1024>>>(h, W, bfc, asrc, adst);
    sortK<<<BB, 1024>>>();
    scanK<<<BB * 65, 256>>>();
    outK<<<(BB * NN) / 8, 256>>>(battn, out);
}

// round 9
// speedup vs baseline: 1.9425x; 1.0786x over previous
#include <cuda_runtime.h>
#include <math.h>

#define BB 8
#define NN 2048
#define IND 128
#define OUTD 64
#define NEG_SLOPE 0.2f

// ---------------- scratch (static device globals; no allocations) ----------------
__device__ float g_hp[BB * NN * OUTD];           // projected features [row][dim] (4 MB)
__device__ float g_hpT[BB * OUTD * NN];          // transposed [b][dim][row] (4 MB)
__device__ float g_s[BB * NN];
__device__ float g_d[BB * NN];
__device__ float g_sortedD[BB * NN];
__device__ int   g_sortIdx[BB * NN];
__device__ float g_wp[BB * NN];                  // exp(d) at sorted position
__device__ float g_wq[BB * NN];                  // exp(0.2 d) at sorted position
__device__ float g_tab[(size_t)BB * 2049 * 130]; // [b][k][0..64]=sufPos, [65..129]=prefNeg

// ---------------- kernel 1: hp = h @ W_fc + b_fc, fused s/d + hpT epilogues ----------
__global__ void projectK(const float* __restrict__ h, const float* __restrict__ W,
                         const float* __restrict__ bfc,
                         const float* __restrict__ asrc, const float* __restrict__ adst) {
    extern __shared__ float sm[];
    float* sH = sm;                 // [64][128]  (32 KB)
    float* sW = sm + 64 * IND;      // [128][64]  (32 KB)
    const int t = threadIdx.x;
    const int rowBase = blockIdx.x * 64;

    const float4* hsrc = (const float4*)(h + (size_t)rowBase * IND);
    float4* sH4 = (float4*)sH;
#pragma unroll
    for (int i = t; i < 64 * IND / 4; i += 256) sH4[i] = hsrc[i];
    const float4* wsrc = (const float4*)W;
    float4* sW4 = (float4*)sW;
#pragma unroll
    for (int i = t; i < IND * OUTD / 4; i += 256) sW4[i] = wsrc[i];
    __syncthreads();

    const int q = t & 15;     // col quad: cols 4q..4q+3
    const int g = t >> 4;     // row group: rows 4g..4g+3
    const int c0 = q * 4;
    const int r0 = g * 4;

    const float4 b4 = *(const float4*)(bfc + c0);
    float acc[4][4];
#pragma unroll
    for (int r = 0; r < 4; r++) {
        acc[r][0] = b4.x; acc[r][1] = b4.y; acc[r][2] = b4.z; acc[r][3] = b4.w;
    }

    for (int k = 0; k < IND; k += 4) {
        float hv[4][4], wv[4][4];
#pragma unroll
        for (int r = 0; r < 4; r++) {
            const float4 a = *(const float4*)&sH[(r0 + r) * IND + k];
            hv[r][0] = a.x; hv[r][1] = a.y; hv[r][2] = a.z; hv[r][3] = a.w;
        }
#pragma unroll
        for (int kk = 0; kk < 4; kk++) {
            const float4 w = *(const float4*)&sW[(k + kk) * OUTD + c0];
            wv[kk][0] = w.x; wv[kk][1] = w.y; wv[kk][2] = w.z; wv[kk][3] = w.w;
        }
#pragma unroll
        for (int kk = 0; kk < 4; kk++)
#pragma unroll
            for (int r = 0; r < 4; r++)
#pragma unroll
                for (int c = 0; c < 4; c++)
                    acc[r][c] = fmaf(hv[r][kk], wv[kk][c], acc[r][c]);
    }

    float* outp = g_hp + (size_t)rowBase * OUTD;
#pragma unroll
    for (int r = 0; r < 4; r++) {
        float4 o; o.x = acc[r][0]; o.y = acc[r][1]; o.z = acc[r][2]; o.w = acc[r][3];
        *(float4*)&outp[(size_t)(r0 + r) * OUTD + c0] = o;
    }

    // ---- fused s/d epilogue: 16-lane shuffle reduce across col-quads ----
    const float4 as4 = *(const float4*)(asrc + c0);
    const float4 ad4 = *(const float4*)(adst + c0);
    float sp[4], dp[4];
#pragma unroll
    for (int r = 0; r < 4; r++) {
        sp[r] = fmaf(acc[r][0], as4.x, fmaf(acc[r][1], as4.y,
                 fmaf(acc[r][2], as4.z, acc[r][3] * as4.w)));
        dp[r] = fmaf(acc[r][0], ad4.x, fmaf(acc[r][1], ad4.y,
                 fmaf(acc[r][2], ad4.z, acc[r][3] * ad4.w)));
    }
#pragma unroll
    for (int o = 1; o < 16; o <<= 1) {
#pragma unroll
        for (int r = 0; r < 4; r++) {
            sp[r] += __shfl_xor_sync(0xffffffffu, sp[r], o);
            dp[r] += __shfl_xor_sync(0xffffffffu, dp[r], o);
        }
    }
    if (q == 0) {
#pragma unroll
        for (int r = 0; r < 4; r++) {
            g_s[rowBase + r0 + r] = sp[r];
            g_d[rowBase + r0 + r] = dp[r];
        }
    }

    // ---- transpose epilogue: emit g_hpT[b][dim][row] ----
    __syncthreads();                    // done reading sH
    float* tile = sm;                   // [64 dims][65 pad]
#pragma unroll
    for (int r = 0; r < 4; r++)
#pragma unroll
        for (int c = 0; c < 4; c++)
            tile[(c0 + c) * 65 + (r0 + r)] = acc[r][c];
    __syncthreads();

    const int b = rowBase >> 11;
    const int rib = rowBase & (NN - 1);
    for (int f = t; f < 64 * 64; f += 256) {
        const int dim = f >> 6, i = f & 63;
        g_hpT[((size_t)(b * OUTD + dim)) * NN + rib + i] = tile[dim * 65 + i];
    }
}

// ---------------- kernel 2: per-batch bitonic sort, packed 64-bit (key|idx) ----------------
__global__ void sortK() {
    const int b = blockIdx.x;
    __shared__ unsigned long long su[NN];
    const int t = threadIdx.x;  // 1024

    for (int i = t; i < NN; i += 1024) {
        const unsigned bits = __float_as_uint(g_d[b * NN + i]);
        const unsigned key = bits ^ ((bits & 0x80000000u) ? 0xFFFFFFFFu : 0x80000000u);
        su[i] = ((unsigned long long)key << 32) | (unsigned)i;
    }
    __syncthreads();

    for (int k = 2; k <= NN; k <<= 1) {
        for (int j = k >> 1; j > 0; j >>= 1) {
            const int i = ((t & ~(j - 1)) << 1) | (t & (j - 1));
            const int partner = i | j;
            const bool up = ((i & k) == 0);
            const unsigned long long A = su[i], B = su[partner];
            const unsigned long long lo_ = (A < B) ? A : B;
            const unsigned long long hi_ = (A < B) ? B : A;
            su[i] = up ? lo_ : hi_;
            su[partner] = up ? hi_ : lo_;
            if (j >= 64) __syncthreads(); else __syncwarp();
        }
        __syncthreads();
    }

    for (int i = t; i < NN; i += 1024) {
        const unsigned long long u = su[i];
        const unsigned key = (unsigned)(u >> 32);
        const unsigned bits = key ^ ((key & 0x80000000u) ? 0x80000000u : 0xFFFFFFFFu);
        const float dv = __uint_as_float(bits);
        g_sortedD[b * NN + i] = dv;
        g_sortIdx[b * NN + i] = (int)(u & 0xFFFFFFFFu);
        g_wp[b * NN + i] = __expf(dv);
        g_wq[b * NN + i] = __expf(NEG_SLOPE * dv);
    }
}

// ---------------- kernel 3: fused dual scan, hpT-row gather (L1-resident) ----------
// block = (b, dim). 256 threads x 8 consecutive sorted positions each.
__global__ void scanK() {
    const int blk = blockIdx.x;          // 0..519
    const int b = blk / 65;
    const int dim = blk - b * 65;
    const int t = threadIdx.x;
    const int lane = t & 31, warp = t >> 5;
    const int base = b * NN;
    const float* __restrict__ hprow = g_hpT + ((size_t)(b * OUTD + dim)) * NN;

    float vp[8], vn[8];
#pragma unroll
    for (int e = 0; e < 8; e++) {
        const int r = t * 8 + e;
        const float wpv = g_wp[base + r];
        const float wqv = g_wq[base + r];
        float val = 1.0f;
        if (dim < 64) val = hprow[g_sortIdx[base + r]];  // scattered within one 8KB L1-resident row
        vp[e] = wpv * val;
        vn[e] = wqv * val;
    }

    // neg: forward inclusive within chunk; pos: backward inclusive (suffix)
#pragma unroll
    for (int e = 1; e < 8; e++) vn[e] += vn[e - 1];
#pragma unroll
    for (int e = 6; e >= 0; e--) vp[e] += vp[e + 1];
    const float totn = vn[7], totp = vp[0];

    __shared__ float wtn[8], wtp[8];
    float xn = totn, xp = totp;
#pragma unroll
    for (int o = 1; o < 32; o <<= 1) {
        const float yn = __shfl_up_sync(0xffffffffu, xn, o);
        if (lane >= o) xn += yn;
        const float yp = __shfl_down_sync(0xffffffffu, xp, o);
        if (lane < 32 - o) xp += yp;
    }
    if (lane == 31) wtn[warp] = xn;
    if (lane == 0)  wtp[warp] = xp;
    __syncthreads();

    float offn = 0.f, offp = 0.f;
#pragma unroll
    for (int w2 = 0; w2 < 8; w2++) {
        if (w2 < warp) offn += wtn[w2];
        if (w2 > warp) offp += wtp[w2];
    }
    const float basen = offn + xn - totn;   // sum strictly before this chunk
    const float basep = offp + xp - totp;   // sum strictly after this chunk

    float* tabb = g_tab + (size_t)b * 2049 * 130;
#pragma unroll
    for (int e = 0; e < 8; e++) {
        const int kp = t * 8 + e;
        tabb[(size_t)kp * 130 + dim] = basep + vp[e];              // sufPos[k]
        tabb[(size_t)(kp + 1) * 130 + 65 + dim] = basen + vn[e];   // prefNeg[k+1]
    }
    if (t == 0) {
        tabb[(size_t)2048 * 130 + dim] = 0.f;        // sufPos[2048]
        tabb[65 + dim] = 0.f;                        // prefNeg[0]
    }
}

// ---------------- kernel 4: per-row output — warp-parallel 3-round search ----------
__global__ void outK(const float* __restrict__ battn, float* __restrict__ out) {
    const int warp = threadIdx.x >> 5, lane = threadIdx.x & 31;
    const int row = blockIdx.x * 8 + warp;
    const int b = row >> 11;                       // NN = 2048

    const float si = g_s[row] + *battn;
    const float tt = -si;                          // d_j >= tt -> positive branch
    const float* __restrict__ sd = g_sortedD + b * NN;

    // warp-cooperative search: lo = first index with sd[lo] >= tt
    int lo;
    {
        // round 1: block ends at lane*64+63; full-block-below count = popc
        const unsigned bal1 = __ballot_sync(0xffffffffu, sd[lane * 64 + 63] < tt);
        const int c1 = __popc(bal1);
        if (c1 == 32) {
            lo = NN;                                // every element < tt
        } else {
            const int w0 = c1 * 64;
            // round 2: stride-2 probes inside the 64-block (offsets 1,3,...,63)
            const unsigned bal2 = __ballot_sync(0xffffffffu, sd[w0 + lane * 2 + 1] < tt);
            const int c2 = __popc(bal2);            // <= 31 (round 1 guarantees)
            // round 3: resolve the remaining pair
            lo = w0 + 2 * c2 + ((sd[w0 + 2 * c2] < tt) ? 1 : 0);
        }
    }

    const float P = __expf(si);
    const float Q = __expf(NEG_SLOPE * si);
    const float* __restrict__ tb = g_tab + ((size_t)b * 2049 + lo) * 130;
    const float den = fmaf(P, tb[64], Q * tb[129]);
    const float inv = 1.0f / den;

    float* orow = out + (size_t)row * OUTD;
#pragma unroll
    for (int d0 = 0; d0 < 2; d0++) {
        const int d = lane + d0 * 32;
        const float num = fmaf(P, tb[d], Q * tb[65 + d]);
        const float o = num * inv;
        orow[d] = (o > 0.f) ? o : (__expf(o) - 1.0f);   // ELU (alpha=1)
    }
}

// ---------------- launch ----------------
extern "C" void kernel_launch(void* const* d_in, const int* in_sizes, int n_in,
                              void* d_out, int out_size) {
    const float* h     = (const float*)d_in[0];
    const float* W     = (const float*)d_in[1];
    const float* bfc   = (const float*)d_in[2];
    const float* asrc  = (const float*)d_in[3];
    const float* adst  = (const float*)d_in[4];
    const float* battn = (const float*)d_in[5];
    float* out = (float*)d_out;

    cudaFuncSetAttribute(projectK, cudaFuncAttributeMaxDynamicSharedMemorySize, 64 * 1024);

    projectK<<<(BB * NN) / 64, 256, 64 * 1024>>>(h, W, bfc, asrc, adst);
    sortK<<<BB, 1024>>>();
    scanK<<<BB * 65, 256>>>();
    outK<<<(BB * NN) / 8, 256>>>(battn, out);
}

// round 10
// speedup vs baseline: 2.4221x; 1.2469x over previous
#include <cuda_runtime.h>
#include <math.h>

#define BB 8
#define NN 2048
#define IND 128
#define OUTD 64
#define NEG_SLOPE 0.2f
#define TABS 136        // padded tab row: [0..64]=sufPos, [68..132]=prefNeg

// ---------------- scratch (static device globals; no allocations) ----------------
__device__ float g_hp[BB * NN * OUTD];           // projected features [row][dim] (4 MB)
__device__ float g_hpT[BB * OUTD * NN];          // transposed [b][dim][row] (4 MB)
__device__ float g_s[BB * NN];
__device__ float g_d[BB * NN];
__device__ float g_sortedD[BB * NN];
__device__ float g_split[BB * 32];               // splitters: sd[64i+63] per batch
__device__ int   g_sortIdx[BB * NN];
__device__ float g_wp[BB * NN];                  // exp(d) at sorted position
__device__ float g_wq[BB * NN];                  // exp(0.2 d) at sorted position
__device__ float g_tab[(size_t)BB * 2049 * TABS];// (8.9 MB)

// ---------------- kernel 1: hp = h @ W_fc + b_fc, fused s/d + hpT epilogues ----------
__global__ void projectK(const float* __restrict__ h, const float* __restrict__ W,
                         const float* __restrict__ bfc,
                         const float* __restrict__ asrc, const float* __restrict__ adst) {
    extern __shared__ float sm[];
    float* sH = sm;                 // [64][128]  (32 KB)
    float* sW = sm + 64 * IND;      // [128][64]  (32 KB)
    const int t = threadIdx.x;
    const int rowBase = blockIdx.x * 64;

    const float4* hsrc = (const float4*)(h + (size_t)rowBase * IND);
    float4* sH4 = (float4*)sH;
#pragma unroll
    for (int i = t; i < 64 * IND / 4; i += 256) sH4[i] = hsrc[i];
    const float4* wsrc = (const float4*)W;
    float4* sW4 = (float4*)sW;
#pragma unroll
    for (int i = t; i < IND * OUTD / 4; i += 256) sW4[i] = wsrc[i];
    __syncthreads();

    const int q = t & 15;     // col quad: cols 4q..4q+3
    const int g = t >> 4;     // row group: rows 4g..4g+3
    const int c0 = q * 4;
    const int r0 = g * 4;

    const float4 b4 = *(const float4*)(bfc + c0);
    float acc[4][4];
#pragma unroll
    for (int r = 0; r < 4; r++) {
        acc[r][0] = b4.x; acc[r][1] = b4.y; acc[r][2] = b4.z; acc[r][3] = b4.w;
    }

    for (int k = 0; k < IND; k += 4) {
        float hv[4][4], wv[4][4];
#pragma unroll
        for (int r = 0; r < 4; r++) {
            const float4 a = *(const float4*)&sH[(r0 + r) * IND + k];
            hv[r][0] = a.x; hv[r][1] = a.y; hv[r][2] = a.z; hv[r][3] = a.w;
        }
#pragma unroll
        for (int kk = 0; kk < 4; kk++) {
            const float4 w = *(const float4*)&sW[(k + kk) * OUTD + c0];
            wv[kk][0] = w.x; wv[kk][1] = w.y; wv[kk][2] = w.z; wv[kk][3] = w.w;
        }
#pragma unroll
        for (int kk = 0; kk < 4; kk++)
#pragma unroll
            for (int r = 0; r < 4; r++)
#pragma unroll
                for (int c = 0; c < 4; c++)
                    acc[r][c] = fmaf(hv[r][kk], wv[kk][c], acc[r][c]);
    }

    float* outp = g_hp + (size_t)rowBase * OUTD;
#pragma unroll
    for (int r = 0; r < 4; r++) {
        float4 o; o.x = acc[r][0]; o.y = acc[r][1]; o.z = acc[r][2]; o.w = acc[r][3];
        *(float4*)&outp[(size_t)(r0 + r) * OUTD + c0] = o;
    }

    // ---- fused s/d epilogue: 16-lane shuffle reduce across col-quads ----
    const float4 as4 = *(const float4*)(asrc + c0);
    const float4 ad4 = *(const float4*)(adst + c0);
    float sp[4], dp[4];
#pragma unroll
    for (int r = 0; r < 4; r++) {
        sp[r] = fmaf(acc[r][0], as4.x, fmaf(acc[r][1], as4.y,
                 fmaf(acc[r][2], as4.z, acc[r][3] * as4.w)));
        dp[r] = fmaf(acc[r][0], ad4.x, fmaf(acc[r][1], ad4.y,
                 fmaf(acc[r][2], ad4.z, acc[r][3] * ad4.w)));
    }
#pragma unroll
    for (int o = 1; o < 16; o <<= 1) {
#pragma unroll
        for (int r = 0; r < 4; r++) {
            sp[r] += __shfl_xor_sync(0xffffffffu, sp[r], o);
            dp[r] += __shfl_xor_sync(0xffffffffu, dp[r], o);
        }
    }
    if (q == 0) {
#pragma unroll
        for (int r = 0; r < 4; r++) {
            g_s[rowBase + r0 + r] = sp[r];
            g_d[rowBase + r0 + r] = dp[r];
        }
    }

    // ---- transpose epilogue: emit g_hpT[b][dim][row] ----
    __syncthreads();                    // done reading sH
    float* tile = sm;                   // [64 dims][65 pad]
#pragma unroll
    for (int r = 0; r < 4; r++)
#pragma unroll
        for (int c = 0; c < 4; c++)
            tile[(c0 + c) * 65 + (r0 + r)] = acc[r][c];
    __syncthreads();

    const int b = rowBase >> 11;
    const int rib = rowBase & (NN - 1);
    for (int f = t; f < 64 * 64; f += 256) {
        const int dim = f >> 6, i = f & 63;
        g_hpT[((size_t)(b * OUTD + dim)) * NN + rib + i] = tile[dim * 65 + i];
    }
}

// ---------------- kernel 2: per-batch bitonic sort, packed 64-bit (key|idx) ----------------
__global__ void sortK() {
    const int b = blockIdx.x;
    __shared__ unsigned long long su[NN];
    const int t = threadIdx.x;  // 1024

    for (int i = t; i < NN; i += 1024) {
        const unsigned bits = __float_as_uint(g_d[b * NN + i]);
        const unsigned key = bits ^ ((bits & 0x80000000u) ? 0xFFFFFFFFu : 0x80000000u);
        su[i] = ((unsigned long long)key << 32) | (unsigned)i;
    }
    __syncthreads();

    for (int k = 2; k <= NN; k <<= 1) {
        for (int j = k >> 1; j > 0; j >>= 1) {
            const int i = ((t & ~(j - 1)) << 1) | (t & (j - 1));
            const int partner = i | j;
            const bool up = ((i & k) == 0);
            const unsigned long long A = su[i], B = su[partner];
            const unsigned long long lo_ = (A < B) ? A : B;
            const unsigned long long hi_ = (A < B) ? B : A;
            su[i] = up ? lo_ : hi_;
            su[partner] = up ? hi_ : lo_;
            if (j >= 64) __syncthreads(); else __syncwarp();
        }
        __syncthreads();
    }

    for (int i = t; i < NN; i += 1024) {
        const unsigned long long u = su[i];
        const unsigned key = (unsigned)(u >> 32);
        const unsigned bits = key ^ ((key & 0x80000000u) ? 0x80000000u : 0xFFFFFFFFu);
        const float dv = __uint_as_float(bits);
        g_sortedD[b * NN + i] = dv;
        g_sortIdx[b * NN + i] = (int)(u & 0xFFFFFFFFu);
        g_wp[b * NN + i] = __expf(dv);
        g_wq[b * NN + i] = __expf(NEG_SLOPE * dv);
        if ((i & 63) == 63) g_split[b * 32 + (i >> 6)] = dv;   // splitter table
    }
}

// ---------------- kernel 3: fused dual scan, 4 dims per block, float4 tab stores ----
// blockIdx.x = b*17 + g. g<16: dims 4g..4g+3. g==16: weight series (val=1).
__global__ void scanK() {
    const int blk = blockIdx.x;
    const int b = blk / 17;
    const int g = blk - b * 17;
    const int t = threadIdx.x;           // 256, each owns 8 consecutive positions
    const int lane = t & 31, warp = t >> 5;
    const int base = b * NN;
    float* tabb = g_tab + (size_t)b * 2049 * TABS;

    if (g < 16) {
        const int d0 = g * 4;
        const float* __restrict__ hp0 = g_hpT + ((size_t)(b * OUTD + d0)) * NN;

        float vp[4][8], vn[4][8];
#pragma unroll
        for (int e = 0; e < 8; e++) {
            const int r = t * 8 + e;
            const float wpv = g_wp[base + r];
            const float wqv = g_wq[base + r];
            const int j = g_sortIdx[base + r];
#pragma unroll
            for (int d = 0; d < 4; d++) {
                const float val = hp0[(size_t)d * NN + j];   // 4x 8KB L1-resident rows
                vp[d][e] = wpv * val;
                vn[d][e] = wqv * val;
            }
        }

        // intra-chunk scans: neg forward, pos backward
#pragma unroll
        for (int d = 0; d < 4; d++) {
#pragma unroll
            for (int e = 1; e < 8; e++) vn[d][e] += vn[d][e - 1];
#pragma unroll
            for (int e = 6; e >= 0; e--) vp[d][e] += vp[d][e + 1];
        }

        __shared__ float wtn[4][8], wtp[4][8];
        float xn[4], xp[4], totn[4], totp[4];
#pragma unroll
        for (int d = 0; d < 4; d++) { totn[d] = vn[d][7]; totp[d] = vp[d][0];
                                      xn[d] = totn[d];    xp[d] = totp[d]; }
#pragma unroll
        for (int o = 1; o < 32; o <<= 1) {
#pragma unroll
            for (int d = 0; d < 4; d++) {
                const float yn = __shfl_up_sync(0xffffffffu, xn[d], o);
                if (lane >= o) xn[d] += yn;
                const float yp = __shfl_down_sync(0xffffffffu, xp[d], o);
                if (lane < 32 - o) xp[d] += yp;
            }
        }
        if (lane == 31) { wtn[0][warp] = xn[0]; wtn[1][warp] = xn[1];
                          wtn[2][warp] = xn[2]; wtn[3][warp] = xn[3]; }
        if (lane == 0)  { wtp[0][warp] = xp[0]; wtp[1][warp] = xp[1];
                          wtp[2][warp] = xp[2]; wtp[3][warp] = xp[3]; }
        __syncthreads();

        float basen[4], basep[4];
#pragma unroll
        for (int d = 0; d < 4; d++) {
            float offn = 0.f, offp = 0.f;
#pragma unroll
            for (int w2 = 0; w2 < 8; w2++) {
                if (w2 < warp) offn += wtn[d][w2];
                if (w2 > warp) offp += wtp[d][w2];
            }
            basen[d] = offn + xn[d] - totn[d];
            basep[d] = offp + xp[d] - totp[d];
        }

#pragma unroll
        for (int e = 0; e < 8; e++) {
            const int kp = t * 8 + e;
            float4 s4; s4.x = basep[0] + vp[0][e]; s4.y = basep[1] + vp[1][e];
                       s4.z = basep[2] + vp[2][e]; s4.w = basep[3] + vp[3][e];
            *(float4*)&tabb[(size_t)kp * TABS + d0] = s4;                 // sufPos[k]
            float4 n4; n4.x = basen[0] + vn[0][e]; n4.y = basen[1] + vn[1][e];
                       n4.z = basen[2] + vn[2][e]; n4.w = basen[3] + vn[3][e];
            *(float4*)&tabb[(size_t)(kp + 1) * TABS + 68 + d0] = n4;      // prefNeg[k+1]
        }
        if (t == 0) {
            const float4 z = {0.f, 0.f, 0.f, 0.f};
            *(float4*)&tabb[(size_t)2048 * TABS + d0] = z;    // sufPos[2048]
            *(float4*)&tabb[68 + d0] = z;                      // prefNeg[0]
        }
    } else {
        // weight series: val = 1 -> scan wp (suffix) and wq (prefix) directly
        float vp[8], vn[8];
#pragma unroll
        for (int e = 0; e < 8; e++) {
            const int r = t * 8 + e;
            vp[e] = g_wp[base + r];
            vn[e] = g_wq[base + r];
        }
#pragma unroll
        for (int e = 1; e < 8; e++) vn[e] += vn[e - 1];
#pragma unroll
        for (int e = 6; e >= 0; e--) vp[e] += vp[e + 1];
        const float totn = vn[7], totp = vp[0];

        __shared__ float wtn1[8], wtp1[8];
        float xn = totn, xp = totp;
#pragma unroll
        for (int o = 1; o < 32; o <<= 1) {
            const float yn = __shfl_up_sync(0xffffffffu, xn, o);
            if (lane >= o) xn += yn;
            const float yp = __shfl_down_sync(0xffffffffu, xp, o);
            if (lane < 32 - o) xp += yp;
        }
        if (lane == 31) wtn1[warp] = xn;
        if (lane == 0)  wtp1[warp] = xp;
        __syncthreads();

        float offn = 0.f, offp = 0.f;
#pragma unroll
        for (int w2 = 0; w2 < 8; w2++) {
            if (w2 < warp) offn += wtn1[w2];
            if (w2 > warp) offp += wtp1[w2];
        }
        const float basen = offn + xn - totn;
        const float basep = offp + xp - totp;

#pragma unroll
        for (int e = 0; e < 8; e++) {
            const int kp = t * 8 + e;
            tabb[(size_t)kp * TABS + 64] = basep + vp[e];               // sufPos weight
            tabb[(size_t)(kp + 1) * TABS + 68 + 64] = basen + vn[e];    // prefNeg weight
        }
        if (t == 0) {
            tabb[(size_t)2048 * TABS + 64] = 0.f;
            tabb[68 + 64] = 0.f;
        }
    }
}

// ---------------- kernel 4: per-row output — splitter + warp-parallel search ----------
__global__ void outK(const float* __restrict__ battn, float* __restrict__ out) {
    const int warp = threadIdx.x >> 5, lane = threadIdx.x & 31;
    const int row = blockIdx.x * 8 + warp;
    const int b = row >> 11;                       // NN = 2048

    const float si = g_s[row] + *battn;
    const float tt = -si;                          // d_j >= tt -> positive branch
    const float* __restrict__ sd = g_sortedD + b * NN;

    // round 1: compact splitter table (single 128B line per batch)
    int lo;
    const unsigned bal1 = __ballot_sync(0xffffffffu, g_split[b * 32 + lane] < tt);
    const int c1 = __popc(bal1);
    if (c1 == 32) {
        lo = NN;
    } else {
        const int w0 = c1 * 64;
        // round 2: stride-2 probes within the 64-block
        const unsigned bal2 = __ballot_sync(0xffffffffu, sd[w0 + lane * 2 + 1] < tt);
        const int c2 = __popc(bal2);               // <= 31 by round-1 guarantee
        // round 3: resolve the remaining pair
        lo = w0 + 2 * c2 + ((sd[w0 + 2 * c2] < tt) ? 1 : 0);
    }

    const float P = __expf(si);
    const float Q = __expf(NEG_SLOPE * si);
    const float* __restrict__ tb = g_tab + ((size_t)b * 2049 + lo) * TABS;
    const float den = fmaf(P, tb[64], Q * tb[68 + 64]);
    const float inv = 1.0f / den;

    float* orow = out + (size_t)row * OUTD;
#pragma unroll
    for (int d0 = 0; d0 < 2; d0++) {
        const int d = lane + d0 * 32;
        const float num = fmaf(P, tb[d], Q * tb[68 + d]);
        const float o = num * inv;
        orow[d] = (o > 0.f) ? o : (__expf(o) - 1.0f);   // ELU (alpha=1)
    }
}

// ---------------- launch ----------------
extern "C" void kernel_launch(void* const* d_in, const int* in_sizes, int n_in,
                              void* d_out, int out_size) {
    const float* h     = (const float*)d_in[0];
    const float* W     = (const float*)d_in[1];
    const float* bfc   = (const float*)d_in[2];
    const float* asrc  = (const float*)d_in[3];
    const float* adst  = (const float*)d_in[4];
    const float* battn = (const float*)d_in[5];
    float* out = (float*)d_out;

    cudaFuncSetAttribute(projectK, cudaFuncAttributeMaxDynamicSharedMemorySize, 64 * 1024);

    projectK<<<(BB * NN) / 64, 256, 64 * 1024>>>(h, W, bfc, asrc, adst);
    sortK<<<BB, 1024>>>();
    scanK<<<BB * 17, 256>>>();
    outK<<<(BB * NN) / 8, 256>>>(battn, out);
}